// round 2
// baseline (speedup 1.0000x reference)
#include <cuda_runtime.h>
#include <cuda_bf16.h>
#include <cstdint>

#define BS     64
#define HH     320
#define WW     320
#define HW     (HH*WW)
#define NCELL  (BS*HW)
#define NT     128
#define BUF_CAP (1<<18)
#define RLIM    (1u<<18)

__device__ __align__(16) unsigned char g_pos[NCELL];
__device__ unsigned long long g_buf[BUF_CAP];
__device__ unsigned int  g_exact[RLIM];
__device__ unsigned int  g_hist[256];
__device__ unsigned int  g_mmap[HW];
__device__ unsigned int  g_bufcnt;
__device__ int           g_numpos;
__device__ unsigned int  g_rstar;
__device__ int           g_need;
__device__ unsigned int  g_tie[256];
__device__ unsigned int  g_tiecnt;
__device__ unsigned long long g_thresh;
__device__ float g_cls;
__device__ float g_reg;

__device__ __forceinline__ float blockReduceSum(float v) {
    __shared__ float s[32];
    int lane = threadIdx.x & 31, wid = threadIdx.x >> 5;
    #pragma unroll
    for (int o = 16; o > 0; o >>= 1) v += __shfl_down_sync(0xFFFFFFFFu, v, o);
    if (lane == 0) s[wid] = v;
    __syncthreads();
    int nw = blockDim.x >> 5;
    v = (threadIdx.x < (unsigned)nw) ? s[threadIdx.x] : 0.0f;
    if (wid == 0) {
        #pragma unroll
        for (int o = 16; o > 0; o >>= 1) v += __shfl_down_sync(0xFFFFFFFFu, v, o);
    }
    return v;
}

// threefry-2x32 with key (0, 42) == jax.random.key(42)
__device__ __forceinline__ void threefry42(unsigned x0, unsigned x1,
                                           unsigned& o0, unsigned& o1) {
    const unsigned ks0 = 0u, ks1 = 42u, ks2 = 0x1BD11BDAu ^ 42u;
    x0 += ks0; x1 += ks1;
#define TF_RND(r) { x0 += x1; x1 = __funnelshift_l(x1, x1, (r)); x1 ^= x0; }
    TF_RND(13) TF_RND(15) TF_RND(26) TF_RND(6)   x0 += ks1; x1 += ks2 + 1u;
    TF_RND(17) TF_RND(29) TF_RND(16) TF_RND(24)  x0 += ks2; x1 += ks0 + 2u;
    TF_RND(13) TF_RND(15) TF_RND(26) TF_RND(6)   x0 += ks0; x1 += ks1 + 3u;
    TF_RND(17) TF_RND(29) TF_RND(16) TF_RND(24)  x0 += ks1; x1 += ks2 + 4u;
    TF_RND(13) TF_RND(15) TF_RND(26) TF_RND(6)   x0 += ks2; x1 += ks0 + 5u;
#undef TF_RND
    o0 = x0; o1 = x1;
}

__global__ void k_zero() {
    unsigned i = blockIdx.x * blockDim.x + threadIdx.x;
    unsigned stride = gridDim.x * blockDim.x;
    uint4 z = make_uint4(0u, 0u, 0u, 0u);
    for (unsigned k = i; k < NCELL / 16; k += stride) ((uint4*)g_pos)[k] = z;
    for (unsigned k = i; k < RLIM; k += stride) g_exact[k] = 0u;
    for (unsigned k = i; k < HW; k += stride) g_mmap[k] = 0u;
    if (i < 256) g_hist[i] = 0u;
    if (i == 0) {
        g_bufcnt = 0u; g_numpos = 0; g_cls = 0.0f; g_reg = 0.0f;
        g_thresh = 0ULL; g_tiecnt = 0u; g_rstar = 0xFFFFFFFFu; g_need = 0;
    }
}

// one block per batch: scatter targets (last-write-wins), count distinct pos, reg loss
__global__ void k_targets(const float* __restrict__ pred,
                          const float* __restrict__ tg) {
    const int b = blockIdx.x, t = threadIdx.x;
    __shared__ int sgx[NT], sgy[NT];
    float tx = tg[(b * NT + t) * 2 + 0];
    float ty = tg[(b * NT + t) * 2 + 1];
    bool valid = (tx >= 0.0f);
    float txw = tx * (float)WW, tyh = ty * (float)HH;
    int gx = min((int)floorf(txw), WW - 1);
    int gy = min((int)floorf(tyh), HH - 1);
    sgx[t] = valid ? gx : -1;
    sgy[t] = gy;
    __syncthreads();
    bool winner = valid;
    if (valid) {
        for (int t2 = t + 1; t2 < NT; t2++)
            if (sgx[t2] == gx && sgy[t2] == gy) { winner = false; break; }
    }
    float reg = 0.0f;
    if (winner) {
        int cell = b * HW + gy * WW + gx;
        g_pos[cell] = 1;
        float ox = txw - (float)gx, oy = tyh - (float)gy;
        float px = pred[(size_t)cell * 3 + 0], py = pred[(size_t)cell * 3 + 1];
        reg = fabsf(px - ox) + fabsf(py - oy);
    }
    int cnt = __syncthreads_count(winner);
    reg = blockReduceSum(reg);
    if (t == 0) { atomicAdd(&g_numpos, cnt); atomicAdd(&g_reg, reg); }
}

// threefry sweep; candidates (r<2^18, non-pos) staged in smem, one global atomic/block
__global__ void __launch_bounds__(256) k_noise() {
    __shared__ unsigned long long sbuf[1024];
    __shared__ unsigned scnt, sbase;
    __shared__ unsigned shist[256];
    const int tid = threadIdx.x;
    if (tid == 0) scnt = 0u;
    shist[tid] = 0u;
    __syncthreads();
    const unsigned base = blockIdx.x * 16384u;
    #pragma unroll 2
    for (int k = 0; k < 16384; k += 256) {
        unsigned i = base + (unsigned)k + (unsigned)tid;
        unsigned o0, o1;
        threefry42(0u, i, o0, o1);
        unsigned r = (o0 ^ o1) >> 9;
        bool want = (r < RLIM) && (g_pos[i] == 0);
        unsigned bal = __ballot_sync(0xFFFFFFFFu, want);
        if (want) {
            atomicAdd(&g_exact[r], 1u);
            atomicAdd(&shist[r >> 10], 1u);
            int lane = tid & 31;
            int leader = __ffs(bal) - 1;
            unsigned p0;
            if (lane == leader) p0 = atomicAdd(&scnt, (unsigned)__popc(bal));
            p0 = __shfl_sync(bal, p0, leader);
            p0 += (unsigned)__popc(bal & ((1u << lane) - 1u));
            if (p0 < 1024u) sbuf[p0] = (((unsigned long long)r) << 23) | i;
        }
    }
    __syncthreads();
    unsigned n = min(scnt, 1024u);
    if (tid == 0) sbase = atomicAdd(&g_bufcnt, n);
    __syncthreads();
    for (unsigned s = tid; s < n; s += 256u)
        if (sbase + s < (unsigned)BUF_CAP) g_buf[sbase + s] = sbuf[s];
    if (shist[tid]) atomicAdd(&g_hist[tid], shist[tid]);
}

// single block: coarse bin scan -> exact in-bin scan -> r*, need
__global__ void k_select() {
    __shared__ unsigned s_scan[1024];
    __shared__ int s_info[3];
    const int tid = threadIdx.x;
    if (tid == 0) {
        long long np = (long long)g_numpos;
        long long nn = 4LL * np;
        long long nonpos = (long long)NCELL - np;
        if (nn > nonpos) nn = nonpos;
        unsigned cum = 0; int B = 255; unsigned before = 0; int found = 0;
        for (int i = 0; i < 256; i++) {
            unsigned c = g_hist[i];
            if (!found && nn > 0 && (long long)(cum + c) >= nn) { B = i; before = cum; found = 1; }
            cum += c;
        }
        s_info[0] = (int)nn; s_info[1] = B; s_info[2] = (int)before;
    }
    __syncthreads();
    int nn = s_info[0], B = s_info[1], before = s_info[2];
    if (nn <= 0) {
        if (tid == 0) { g_thresh = 0ULL; g_need = 0; g_rstar = 0xFFFFFFFFu; }
        return;
    }
    unsigned c = g_exact[B * 1024 + tid];
    s_scan[tid] = c;
    __syncthreads();
    for (int off = 1; off < 1024; off <<= 1) {
        unsigned v = (tid >= off) ? s_scan[tid - off] : 0u;
        __syncthreads();
        s_scan[tid] += v;
        __syncthreads();
    }
    unsigned incl = s_scan[tid];
    unsigned excl = incl - c;
    int target = nn - before;
    if ((int)excl < target && (int)incl >= target) {
        g_rstar = ((unsigned)B << 10) | (unsigned)tid;
        g_need = target - (int)excl;
    }
}

__global__ void k_ties() {
    unsigned cnt = min(g_bufcnt, (unsigned)BUF_CAP);
    unsigned rstar = g_rstar;
    unsigned i = blockIdx.x * blockDim.x + threadIdx.x;
    unsigned stride = gridDim.x * blockDim.x;
    for (; i < cnt; i += stride) {
        unsigned long long pk = g_buf[i];
        if ((unsigned)(pk >> 23) == rstar) {
            unsigned s = atomicAdd(&g_tiecnt, 1u);
            if (s < 256u) g_tie[s] = (unsigned)(pk & 0x7FFFFFu);
        }
    }
}

__global__ void k_thresh() {
    int need = g_need; unsigned rstar = g_rstar;
    if (need <= 0 || rstar == 0xFFFFFFFFu) { g_thresh = 0ULL; return; }
    int n = (int)min(g_tiecnt, 256u);
    unsigned best = 0u;
    for (int a = 0; a < need; a++) {
        int mi = 0; unsigned mv = 0xFFFFFFFFu;
        for (int b = 0; b < n; b++) { unsigned v = g_tie[b]; if (v < mv) { mv = v; mi = b; } }
        g_tie[mi] = 0xFFFFFFFFu; best = mv;
    }
    g_thresh = ((((unsigned long long)rstar) << 23) | best) + 1ULL;
}

__global__ void k_mmap() {
    unsigned cnt = min(g_bufcnt, (unsigned)BUF_CAP);
    unsigned long long th = g_thresh;
    unsigned i = blockIdx.x * blockDim.x + threadIdx.x;
    unsigned stride = gridDim.x * blockDim.x;
    for (; i < cnt; i += stride) {
        unsigned long long pk = g_buf[i];
        if (pk < th) {
            unsigned cell = (unsigned)(pk & 0x7FFFFFu);
            atomicAdd(&g_mmap[cell % (unsigned)HW], 1u);
        }
    }
}

__global__ void __launch_bounds__(256) k_main(const float* __restrict__ pred) {
    int i0 = blockIdx.x * blockDim.x + threadIdx.x;
    int stride = gridDim.x * blockDim.x;
    float acc = 0.0f;
    for (int c = i0; c < NCELL; c += stride) {
        unsigned m = g_mmap[((unsigned)c) % (unsigned)HW];
        if (m) {
            float pc = __ldg(pred + (size_t)c * 3 + 2);
            float t = (float)g_pos[c];
            float bce = fmaxf(pc, 0.0f) - pc * t + __logf(1.0f + __expf(-fabsf(pc)));
            float pt = __expf(-bce);
            float om = 1.0f - pt;
            acc += om * om * bce * (float)m;
        }
    }
    acc = blockReduceSum(acc * 0.25f);
    if (threadIdx.x == 0) atomicAdd(&g_cls, acc);
}

__global__ void k_final(float* out) {
    out[0] = (0.8f * g_cls + 0.2f * g_reg) * (1.0f / (float)BS);
}

extern "C" void kernel_launch(void* const* d_in, const int* in_sizes, int n_in,
                              void* d_out, int out_size) {
    const float* pred = (const float*)d_in[0];
    const float* tg   = (const float*)d_in[1];
    if (n_in >= 2 && in_sizes[0] < in_sizes[1]) {  // defensive: pred is the big one
        pred = (const float*)d_in[1];
        tg   = (const float*)d_in[0];
    }
    k_zero   <<<512, 256>>>();
    k_targets<<<BS, NT>>>(pred, tg);
    k_noise  <<<NCELL / 16384, 256>>>();
    k_select <<<1, 1024>>>();
    k_ties   <<<64, 256>>>();
    k_thresh <<<1, 1>>>();
    k_mmap   <<<64, 256>>>();
    k_main   <<<2048, 256>>>(pred);
    k_final  <<<1, 1>>>((float*)d_out);
}

// round 3
// speedup vs baseline: 1.2956x; 1.2956x over previous
#include <cuda_runtime.h>
#include <cuda_bf16.h>
#include <cstdint>

#define BS     64
#define HH     320
#define WW     320
#define HW     (HH*WW)
#define NCELL  (BS*HW)
#define NT     128
#define BUF_CAP (1<<18)
#define RLIM    (1u<<18)
#define NPWORDS (NCELL/32)

__device__ unsigned g_posbits[NPWORDS];        // 800 KB bitmask
__device__ unsigned long long g_buf[BUF_CAP];  // packed (r<<23)|idx
__device__ unsigned g_exact[RLIM];
__device__ unsigned g_hist[256];
__device__ unsigned g_mmap[HW];
__device__ unsigned g_bufcnt;
__device__ int      g_numpos;
__device__ unsigned g_rstar;
__device__ int      g_need;
__device__ unsigned g_tie[1024];
__device__ unsigned g_tiecnt;
__device__ float    g_cls, g_reg;
__device__ unsigned g_done;

__device__ __forceinline__ float blockReduceSum(float v) {
    __shared__ float s[32];
    int lane = threadIdx.x & 31, wid = threadIdx.x >> 5;
    #pragma unroll
    for (int o = 16; o > 0; o >>= 1) v += __shfl_down_sync(0xFFFFFFFFu, v, o);
    if (lane == 0) s[wid] = v;
    __syncthreads();
    int nw = blockDim.x >> 5;
    v = (threadIdx.x < (unsigned)nw) ? s[threadIdx.x] : 0.0f;
    if (wid == 0) {
        #pragma unroll
        for (int o = 16; o > 0; o >>= 1) v += __shfl_down_sync(0xFFFFFFFFu, v, o);
    }
    return v;
}

// threefry-2x32, key (0,42) == jax.random.key(42), partitionable counter mode
__device__ __forceinline__ unsigned threefry42_xor(unsigned x0, unsigned x1) {
    const unsigned ks0 = 0u, ks1 = 42u, ks2 = 0x1BD11BDAu ^ 42u;
    x0 += ks0; x1 += ks1;
#define TF_RND(r) { x0 += x1; x1 = __funnelshift_l(x1, x1, (r)); x1 ^= x0; }
    TF_RND(13) TF_RND(15) TF_RND(26) TF_RND(6)   x0 += ks1; x1 += ks2 + 1u;
    TF_RND(17) TF_RND(29) TF_RND(16) TF_RND(24)  x0 += ks2; x1 += ks0 + 2u;
    TF_RND(13) TF_RND(15) TF_RND(26) TF_RND(6)   x0 += ks0; x1 += ks1 + 3u;
    TF_RND(17) TF_RND(29) TF_RND(16) TF_RND(24)  x0 += ks1; x1 += ks2 + 4u;
    TF_RND(13) TF_RND(15) TF_RND(26) TF_RND(6)   x0 += ks2; x1 += ks0 + 5u;
#undef TF_RND
    return x0 ^ x1;
}

__global__ void k_zero() {
    unsigned i = blockIdx.x * blockDim.x + threadIdx.x;
    unsigned stride = gridDim.x * blockDim.x;
    uint4 z = make_uint4(0u, 0u, 0u, 0u);
    for (unsigned k = i; k < NPWORDS / 4; k += stride) ((uint4*)g_posbits)[k] = z;
    for (unsigned k = i; k < RLIM / 4;   k += stride) ((uint4*)g_exact)[k]   = z;
    for (unsigned k = i; k < HW / 4;     k += stride) ((uint4*)g_mmap)[k]    = z;
    if (i < 256) g_hist[i] = 0u;
    if (i == 0) {
        g_bufcnt = 0u; g_numpos = 0; g_cls = 0.0f; g_reg = 0.0f;
        g_tiecnt = 0u; g_rstar = 0xFFFFFFFFu; g_need = 0; g_done = 0u;
    }
}

// one block per batch: scatter targets (last-write-wins), distinct-pos count, reg loss
__global__ void k_targets(const float* __restrict__ pred,
                          const float* __restrict__ tg) {
    const int b = blockIdx.x, t = threadIdx.x;
    __shared__ int sgx[NT], sgy[NT];
    float tx = tg[(b * NT + t) * 2 + 0];
    float ty = tg[(b * NT + t) * 2 + 1];
    bool valid = (tx >= 0.0f);
    float txw = tx * (float)WW, tyh = ty * (float)HH;
    int gx = min((int)floorf(txw), WW - 1);
    int gy = min((int)floorf(tyh), HH - 1);
    sgx[t] = valid ? gx : -1;
    sgy[t] = gy;
    __syncthreads();
    bool winner = valid;
    if (valid) {
        for (int t2 = t + 1; t2 < NT; t2++)
            if (sgx[t2] == gx && sgy[t2] == gy) { winner = false; break; }
    }
    float reg = 0.0f;
    if (winner) {
        int cell = b * HW + gy * WW + gx;
        atomicOr(&g_posbits[cell >> 5], 1u << (cell & 31));
        float ox = txw - (float)gx, oy = tyh - (float)gy;
        float px = pred[(size_t)cell * 3 + 0], py = pred[(size_t)cell * 3 + 1];
        reg = fabsf(px - ox) + fabsf(py - oy);
    }
    int cnt = __syncthreads_count(winner);
    reg = blockReduceSum(reg);
    if (t == 0) { atomicAdd(&g_numpos, cnt); atomicAdd(&g_reg, reg); }
}

// threefry sweep; candidates (r<2^18, non-pos) staged in smem, one global atomic/block
__global__ void __launch_bounds__(256) k_noise() {
    __shared__ unsigned long long sbuf[1024];
    __shared__ unsigned scnt, sbase;
    __shared__ unsigned shist[256];
    const int tid = threadIdx.x;
    const int lane = tid & 31;
    if (tid == 0) scnt = 0u;
    shist[tid] = 0u;
    __syncthreads();
    const unsigned base = blockIdx.x * 16384u;
    #pragma unroll 2
    for (int k = 0; k < 16384; k += 256) {
        unsigned i = base + (unsigned)k + (unsigned)tid;
        unsigned r = threefry42_xor(0u, i) >> 9;   // 23-bit sort key
        bool cand = (r < RLIM);
        if (__ballot_sync(0xFFFFFFFFu, cand)) {
            unsigned pw = g_posbits[i >> 5];       // warp-uniform address -> broadcast
            bool want = cand && !((pw >> lane) & 1u);
            unsigned bal = __ballot_sync(0xFFFFFFFFu, want);
            if (want) {
                atomicAdd(&g_exact[r], 1u);
                atomicAdd(&shist[r >> 10], 1u);
                int leader = __ffs(bal) - 1;
                unsigned p0;
                if (lane == leader) p0 = atomicAdd(&scnt, (unsigned)__popc(bal));
                p0 = __shfl_sync(bal, p0, leader);
                p0 += (unsigned)__popc(bal & ((1u << lane) - 1u));
                if (p0 < 1024u) sbuf[p0] = (((unsigned long long)r) << 23) | i;
            }
        }
    }
    __syncthreads();
    unsigned n = min(scnt, 1024u);
    if (tid == 0) sbase = atomicAdd(&g_bufcnt, n);
    __syncthreads();
    for (unsigned s = tid; s < n; s += 256u)
        if (sbase + s < (unsigned)BUF_CAP) g_buf[sbase + s] = sbuf[s];
    if (shist[tid]) atomicAdd(&g_hist[tid], shist[tid]);
}

// single block, fully parallel: coarse scan over 256 bins, then warp-shuffle
// scan over the 1024-entry exact slice -> (r*, need)
__global__ void __launch_bounds__(1024) k_select() {
    __shared__ unsigned h[256];
    __shared__ unsigned wsum[32];
    __shared__ int s_nn, s_B, s_before;
    const int tid = threadIdx.x, lane = tid & 31, wid = tid >> 5;

    unsigned cme = 0u;
    if (tid < 256) { cme = g_hist[tid]; h[tid] = cme; }
    if (tid == 0) {
        long long np = (long long)g_numpos;
        long long nn = 4LL * np;
        long long nonpos = (long long)NCELL - np;
        if (nn > nonpos) nn = nonpos;
        s_nn = (int)nn; s_B = -1; s_before = 0;
    }
    __syncthreads();
    // Hillis-Steele scan over 256 bins (all 1024 threads hit the barriers)
    #pragma unroll
    for (int off = 1; off < 256; off <<= 1) {
        unsigned v = (tid < 256 && tid >= off) ? h[tid - off] : 0u;
        __syncthreads();
        if (tid < 256) h[tid] += v;
        __syncthreads();
    }
    int nn = s_nn;
    if (tid < 256 && nn > 0) {
        unsigned incl = h[tid], excl = incl - cme;
        if ((int)excl < nn && (int)incl >= nn) { s_B = tid; s_before = (int)excl; }
    }
    __syncthreads();
    int B = s_B, before = s_before;
    if (nn <= 0 || B < 0) {
        if (tid == 0) { g_rstar = 0xFFFFFFFFu; g_need = 0; }
        return;
    }
    // exact slice scan: coalesced 4KB load + warp-shuffle scan + warp-offset scan
    unsigned c = g_exact[B * 1024 + tid];
    unsigned v = c;
    #pragma unroll
    for (int o = 1; o < 32; o <<= 1) {
        unsigned n2 = __shfl_up_sync(0xFFFFFFFFu, v, o);
        if (lane >= o) v += n2;
    }
    if (lane == 31) wsum[wid] = v;
    __syncthreads();
    if (wid == 0) {
        unsigned w = wsum[lane];
        #pragma unroll
        for (int o = 1; o < 32; o <<= 1) {
            unsigned n2 = __shfl_up_sync(0xFFFFFFFFu, w, o);
            if (lane >= o) w += n2;
        }
        wsum[lane] = w;
    }
    __syncthreads();
    unsigned incl = v + (wid ? wsum[wid - 1] : 0u);
    unsigned excl = incl - c;
    int target = nn - before;
    if ((int)excl < target && (int)incl >= target) {
        g_rstar = ((unsigned)B << 10) | (unsigned)tid;
        g_need = target - (int)excl;
    }
}

// one pass over candidates: strict r<r* -> mmap; r==r* -> tie list
__global__ void k_mmap_ties() {
    unsigned rstar = g_rstar;
    if (rstar == 0xFFFFFFFFu) return;
    unsigned cnt = min(g_bufcnt, (unsigned)BUF_CAP);
    unsigned i = blockIdx.x * blockDim.x + threadIdx.x;
    unsigned stride = gridDim.x * blockDim.x;
    for (; i < cnt; i += stride) {
        unsigned long long pk = g_buf[i];
        unsigned r = (unsigned)(pk >> 23);
        if (r < rstar) {
            atomicAdd(&g_mmap[(unsigned)(pk & 0x7FFFFFu) % (unsigned)HW], 1u);
        } else if (r == rstar) {
            unsigned s = atomicAdd(&g_tiecnt, 1u);
            if (s < 1024u) g_tie[s] = (unsigned)(pk & 0x7FFFFFu);
        }
    }
}

// resolve stable tie-break: the `need` smallest indices at r* are selected
__global__ void __launch_bounds__(1024) k_tiefix() {
    int need = g_need;
    if (need <= 0 || g_rstar == 0xFFFFFFFFu) return;
    int n = (int)min(g_tiecnt, 1024u);
    int tid = threadIdx.x;
    if (tid < n) {
        unsigned my = g_tie[tid];
        int rank = 0;
        for (int j = 0; j < n; j++) if (g_tie[j] < my) rank++;
        if (rank < need) atomicAdd(&g_mmap[my % (unsigned)HW], 1u);
    }
}

// main sweep: cls = ALPHA * sum_cell fl(cell) * m(pixel); last block emits output.
// Each thread: 4 cells = 12 floats = 3 float4 loads; exact grid, no loop.
__global__ void __launch_bounds__(256) k_main(const float* __restrict__ pred,
                                              float* __restrict__ out) {
    unsigned u = blockIdx.x * 256u + threadIdx.x;     // u in [0, NCELL/4)
    const float4* p4 = (const float4*)pred;
    float4 a = __ldg(p4 + 3u * u + 0u);
    float4 b = __ldg(p4 + 3u * u + 1u);
    float4 cc = __ldg(p4 + 3u * u + 2u);
    uint4 mv = __ldg(((const uint4*)g_mmap) + (u % (unsigned)(HW / 4)));
    unsigned pw = g_posbits[u >> 3];
    unsigned sh = (u & 7u) * 4u;

    float x[4] = { a.z, b.y, cc.x, cc.w };
    unsigned m[4] = { mv.x, mv.y, mv.z, mv.w };
    float acc = 0.0f;
    #pragma unroll
    for (int j = 0; j < 4; j++) {
        if (m[j]) {
            float pc = x[j];
            float t = (float)((pw >> (sh + j)) & 1u);
            float e = __expf(-fabsf(pc));
            float bce = fmaxf(pc, 0.0f) - pc * t + __logf(1.0f + e);
            float pt = __expf(-bce);
            float om = 1.0f - pt;
            acc += om * om * bce * (float)m[j];
        }
    }
    acc = blockReduceSum(acc * 0.25f);                 // ALPHA
    __shared__ bool lastblk;
    if (threadIdx.x == 0) {
        if (acc != 0.0f) atomicAdd(&g_cls, acc);
        __threadfence();
        lastblk = (atomicAdd(&g_done, 1u) == gridDim.x - 1u);
    }
    __syncthreads();
    if (lastblk && threadIdx.x == 0) {
        __threadfence();
        out[0] = (0.8f * g_cls + 0.2f * g_reg) * (1.0f / (float)BS);
    }
}

extern "C" void kernel_launch(void* const* d_in, const int* in_sizes, int n_in,
                              void* d_out, int out_size) {
    const float* pred = (const float*)d_in[0];
    const float* tg   = (const float*)d_in[1];
    if (n_in >= 2 && in_sizes[0] < in_sizes[1]) {   // pred is the big input
        pred = (const float*)d_in[1];
        tg   = (const float*)d_in[0];
    }
    k_zero      <<<512, 256>>>();
    k_targets   <<<BS, NT>>>(pred, tg);
    k_noise     <<<NCELL / 16384, 256>>>();
    k_select    <<<1, 1024>>>();
    k_mmap_ties <<<128, 256>>>();
    k_tiefix    <<<1, 1024>>>();
    k_main      <<<NCELL / 4 / 256, 256>>>(pred, (float*)d_out);
}